// round 5
// baseline (speedup 1.0000x reference)
#include <cuda_runtime.h>
#include <cstdint>

#define N_GT    128
#define TS      64            // tile size (px)
#define NTX     16            // tiles per axis
#define NTILES  256           // 16x16
#define CAP     2048          // bin capacity per tile (avg 1024, 6-sigma ~1216)
#define EXPAND  129.0f        // TS + max anchor extent (65)
#define MT      256           // threads per main block
#define SPLIT   2             // blocks per tile (wave balance)
#define AMAX    4             // CAP / (MT*SPLIT)

__device__ int                g_count[NTILES];
__device__ int                g_bins[NTILES * CAP];
__device__ unsigned           g_mask[NTILES][4];     // 128-bit gt mask per tile
__device__ unsigned long long g_best[N_GT];          // (iou_bits<<32)|(~anchor_idx)

// Per-tile GT candidate masks + clear counters + init best keys.
__global__ void k_prep(const float4* __restrict__ gt) {
    int tile = blockIdx.x;              // 256 tiles
    int tid  = threadIdx.x;             // 128 = one gt per thread
    float tx0 = (float)((tile & (NTX - 1)) * TS);
    float ty0 = (float)((tile >> 4) * TS);
    float4 g = gt[tid];
    // gt can overlap some anchor whose top-left corner lies in this tile iff:
    bool hit = (g.z > tx0) && (g.x < tx0 + EXPAND) &&
               (g.w > ty0) && (g.y < ty0 + EXPAND);
    unsigned b = __ballot_sync(0xFFFFFFFFu, hit);
    if ((tid & 31) == 0) g_mask[tile][tid >> 5] = b;
    if (tid == 0) g_count[tile] = 0;
    if (blockIdx.x == 0) g_best[tid] = 0x00000000FFFFFFFFull; // iou=0, idx=0
}

// Bin anchors by top-left-corner tile.
__global__ void k_scatter(const float4* __restrict__ anchor, int n) {
    int i = blockIdx.x * blockDim.x + threadIdx.x;
    if (i >= n) return;
    float4 a = anchor[i];
    int tx = min((int)a.x >> 6, NTX - 1);
    int ty = min((int)a.y >> 6, NTX - 1);
    int t = ty * NTX + tx;
    int slot = atomicAdd(&g_count[t], 1);
    if (slot < CAP) g_bins[t * CAP + slot] = i;
}

// Sparse pair evaluation: bit-exact fp32 quotient per candidate pair.
__global__ __launch_bounds__(MT) void k_main(
    const float4* __restrict__ anchor,
    const float4* __restrict__ gt,
    float* __restrict__ assign)
{
    __shared__ float s_gx1[N_GT], s_gy1[N_GT], s_gx2[N_GT], s_gy2[N_GT], s_ga[N_GT];
    __shared__ int   s_gid[N_GT];
    __shared__ unsigned long long s_best[N_GT];
    __shared__ int s_nc;

    const int tile = blockIdx.x;
    const int part = blockIdx.y;        // 0..SPLIT-1
    const int tid  = threadIdx.x;
    int count = g_count[tile];
    if (count > CAP) count = CAP;

    if (tid == 0) s_nc = 0;
    __syncthreads();
    if (tid < N_GT) {
        unsigned m = g_mask[tile][tid >> 5];
        if ((m >> (tid & 31)) & 1u) {
            int s = atomicAdd(&s_nc, 1);
            float4 g = gt[tid];
            s_gx1[s] = g.x; s_gy1[s] = g.y;
            s_gx2[s] = g.z; s_gy2[s] = g.w;
            s_ga[s]  = __fmul_rn(__fsub_rn(g.z, g.x), __fsub_rn(g.w, g.y));
            s_gid[s] = tid;
            s_best[s] = 0ull;
        }
    }
    __syncthreads();
    const int ncand = s_nc;

    // Load this thread's anchors into statically-indexed register arrays.
    float4 ab[AMAX]; float aarea[AMAX]; int aidx[AMAX];
    const int base = part * MT + tid;    // slot stride MT*SPLIT
    #pragma unroll
    for (int j = 0; j < AMAX; ++j) {
        int slot = j * (MT * SPLIT) + base;
        if (slot < count) {
            int i = g_bins[tile * CAP + slot];
            float4 a = anchor[i];
            ab[j] = a;
            aarea[j] = __fmul_rn(__fsub_rn(a.z, a.x), __fsub_rn(a.w, a.y));
            aidx[j] = i;
        } else {
            aidx[j] = -1;
        }
    }

    unsigned hitmask = 0;
    for (int c = 0; c < ncand; ++c) {
        const float gx1 = s_gx1[c], gy1 = s_gy1[c];
        const float gx2 = s_gx2[c], gy2 = s_gy2[c], ga = s_ga[c];
        unsigned long long bkey = 0ull;
        #pragma unroll
        for (int j = 0; j < AMAX; ++j) {
            if (aidx[j] >= 0) {
                float4 a = ab[j];
                // exact reference arithmetic (no contraction):
                float w = fmaxf(__fsub_rn(fminf(a.z, gx2), fmaxf(a.x, gx1)), 0.0f);
                float h = fmaxf(__fsub_rn(fminf(a.w, gy2), fmaxf(a.y, gy1)), 0.0f);
                float inter = __fmul_rn(w, h);
                float u = __fsub_rn(__fadd_rn(aarea[j], ga), inter);
                float q = __fdiv_rn(inter, u);          // == jax inter/union bitwise
                if (q >= 0.3f) hitmask |= 1u << j;
                unsigned long long key =
                    ((unsigned long long)__float_as_uint(q) << 32) |
                    (unsigned)(0xFFFFFFFFu - (unsigned)aidx[j]);
                if (key > bkey) bkey = key;             // max iou, then min idx
            }
        }
        // warp max, then one smem atomic per warp
        #pragma unroll
        for (int o = 16; o; o >>= 1) {
            unsigned long long v = __shfl_down_sync(0xFFFFFFFFu, bkey, o);
            if (v > bkey) bkey = v;
        }
        if ((tid & 31) == 0 && bkey) atomicMax(&s_best[c], bkey);
    }
    __syncthreads();
    if (tid < ncand) {
        unsigned long long v = s_best[tid];
        if (v) atomicMax(&g_best[s_gid[tid]], v);
    }

    // Row results: -2 if any iou >= 0.3, else -1 (exact fp32 compare above).
    #pragma unroll
    for (int j = 0; j < AMAX; ++j)
        if (aidx[j] >= 0)
            assign[aidx[j]] = ((hitmask >> j) & 1u) ? -2.0f : -1.0f;
}

// Each gt claims its argmax anchor; int-bits atomicMax == reference .at[].max.
__global__ void k_claim(float* __restrict__ assign, int n) {
    int g = threadIdx.x;
    unsigned long long v = g_best[g];
    unsigned idx = 0xFFFFFFFFu - (unsigned)(v & 0xFFFFFFFFull);
    if (idx < (unsigned)n)
        atomicMax((int*)assign + idx, __float_as_int((float)g));
}

extern "C" void kernel_launch(void* const* d_in, const int* in_sizes, int n_in,
                              void* d_out, int out_size) {
    int ia = (n_in >= 2 && in_sizes[1] > in_sizes[0]) ? 1 : 0;
    const float4* anchor = (const float4*)d_in[ia];       // [N,4] f32
    const float4* gt     = (const float4*)d_in[1 - ia];   // [128,4] f32
    float* assign = (float*)d_out;                        // float32 output
    int n = in_sizes[ia] / 4;                             // 262144

    k_prep<<<NTILES, N_GT>>>(gt);
    k_scatter<<<(n + 255) / 256, 256>>>(anchor, n);
    k_main<<<dim3(NTILES, SPLIT), MT>>>(anchor, gt, assign);
    k_claim<<<1, N_GT>>>(assign, n);
    (void)out_size;
}

// round 6
// speedup vs baseline: 1.0241x; 1.0241x over previous
#include <cuda_runtime.h>
#include <cstdint>

#define N_GT    128
#define NTX     16
#define NTILES  256
#define CAP     2048          // >= max bin count (~1370 @6sigma for 225 live tiles)
#define EXPAND  129.0f        // tile size 64 + max anchor extent 65
#define MT      256
#define SPLIT   2
#define AMAX    4             // CAP / (MT*SPLIT)
#define GRID    (NTILES * SPLIT)   // 512

__device__ int                g_count[NTILES];     // zero-init; invariant restored each run
__device__ int                g_bins[NTILES * CAP];
__device__ unsigned long long g_best[N_GT];
__device__ unsigned           g_gen = 0, g_arrive = 0;

// Grid-wide barrier: monotonic generation counter (replay-safe, self-resetting).
__device__ __forceinline__ void gridbar() {
    __syncthreads();
    if (threadIdx.x == 0) {
        __threadfence();
        unsigned gen = atomicAdd(&g_gen, 0u);
        if (atomicAdd(&g_arrive, 1u) == GRID - 1) {
            g_arrive = 0u;
            __threadfence();
            atomicAdd(&g_gen, 1u);
        } else {
            while (atomicAdd(&g_gen, 0u) == gen) __nanosleep(64);
        }
        __threadfence();
    }
    __syncthreads();
}

__global__ __launch_bounds__(MT, 4) void fused(
    const float4* __restrict__ anchor,
    const float4* __restrict__ gt,
    float* __restrict__ assign, int n)
{
    __shared__ float s_gx1[N_GT], s_gy1[N_GT], s_gx2[N_GT], s_gy2[N_GT], s_ga[N_GT];
    __shared__ int   s_gid[N_GT];
    __shared__ unsigned long long s_best[N_GT];
    __shared__ int s_nc;

    const int tid = threadIdx.x;
    const int b   = blockIdx.x;
    const int lane = tid & 31;

    // ---- P1: init g_best (block 0) + bin anchors (warp-aggregated atomics) ----
    if (b == 0 && tid < N_GT) g_best[tid] = 0x00000000FFFFFFFFull; // iou=0, idx=0

    const int slice = n / GRID;                 // 512
    const int base  = b * slice;
    for (int r = 0; r < slice; r += MT) {
        int i = base + r + tid;
        float4 a = anchor[i];
        int tx = min((int)a.x >> 6, NTX - 1);
        int ty = min((int)a.y >> 6, NTX - 1);
        int t = ty * NTX + tx;
        unsigned grp = __match_any_sync(0xFFFFFFFFu, t);
        int leader = __ffs(grp) - 1;
        int rank = __popc(grp & ((1u << lane) - 1u));
        int sbase = 0;
        if (lane == leader) sbase = atomicAdd(&g_count[t], __popc(grp));
        sbase = __shfl_sync(0xFFFFFFFFu, sbase, leader);
        int slot = sbase + rank;
        if (slot < CAP) g_bins[t * CAP + slot] = i;
        else            assign[i] = -1.0f;      // capacity overflow guard (unreachable)
    }

    gridbar();

    // ---- P2: per-tile sparse IoU (2 blocks per tile) ----
    const int tile = b >> 1;
    const int part = b & 1;
    int count = min(g_count[tile], CAP);

    if (tid == 0) s_nc = 0;
    __syncthreads();
    if (tid < N_GT) {
        float tx0 = (float)((tile & (NTX - 1)) << 6);
        float ty0 = (float)((tile >> 4) << 6);
        float4 g = gt[tid];
        if ((g.z > tx0) & (g.x < tx0 + EXPAND) & (g.w > ty0) & (g.y < ty0 + EXPAND)) {
            int s = atomicAdd(&s_nc, 1);
            s_gx1[s] = g.x; s_gy1[s] = g.y;
            s_gx2[s] = g.z; s_gy2[s] = g.w;
            s_ga[s]  = __fmul_rn(__fsub_rn(g.z, g.x), __fsub_rn(g.w, g.y));
            s_gid[s] = tid;
            s_best[s] = 0ull;
        }
    }
    __syncthreads();
    const int ncand = s_nc;

    float4 ab[AMAX]; float aarea[AMAX]; int aidx[AMAX];
    const int tb = part * MT + tid;             // slot stride MT*SPLIT
    #pragma unroll
    for (int j = 0; j < AMAX; ++j) {
        int slot = j * (MT * SPLIT) + tb;
        if (slot < count) {
            int i = g_bins[tile * CAP + slot];
            float4 a = anchor[i];
            ab[j] = a;
            aarea[j] = __fmul_rn(__fsub_rn(a.z, a.x), __fsub_rn(a.w, a.y));
            aidx[j] = i;
        } else aidx[j] = -1;
    }

    unsigned hitmask = 0;
    for (int c = 0; c < ncand; ++c) {
        const float gx1 = s_gx1[c], gy1 = s_gy1[c];
        const float gx2 = s_gx2[c], gy2 = s_gy2[c], ga = s_ga[c];
        unsigned long long bkey = 0ull;
        #pragma unroll
        for (int j = 0; j < AMAX; ++j) {
            if (aidx[j] >= 0) {
                float4 a = ab[j];
                // bit-exact reference arithmetic:
                float w = fmaxf(__fsub_rn(fminf(a.z, gx2), fmaxf(a.x, gx1)), 0.0f);
                float h = fmaxf(__fsub_rn(fminf(a.w, gy2), fmaxf(a.y, gy1)), 0.0f);
                float inter = __fmul_rn(w, h);
                float u = __fsub_rn(__fadd_rn(aarea[j], ga), inter);
                float q = __fdiv_rn(inter, u);         // == jax fp32 inter/union
                if (q >= 0.3f) hitmask |= 1u << j;
                unsigned long long key =
                    ((unsigned long long)__float_as_uint(q) << 32) |
                    (unsigned)(0xFFFFFFFFu - (unsigned)aidx[j]);
                if (key > bkey) bkey = key;            // max iou, then min idx
            }
        }
        #pragma unroll
        for (int o = 16; o; o >>= 1) {
            unsigned long long v = __shfl_down_sync(0xFFFFFFFFu, bkey, o);
            if (v > bkey) bkey = v;
        }
        if (lane == 0 && bkey) atomicMax(&s_best[c], bkey);
    }
    __syncthreads();
    if (tid < ncand) {
        unsigned long long v = s_best[tid];
        if (v) atomicMax(&g_best[s_gid[tid]], v);
    }

    // Row results (-2 if any exact iou >= 0.3, else -1); every anchor covered.
    #pragma unroll
    for (int j = 0; j < AMAX; ++j)
        if (aidx[j] >= 0)
            assign[aidx[j]] = ((hitmask >> j) & 1u) ? -2.0f : -1.0f;

    gridbar();

    // ---- P3: claim argmax anchors + restore counter invariant ----
    if (b == 0) {
        if (tid < N_GT) {
            unsigned long long v = g_best[tid];
            unsigned idx = 0xFFFFFFFFu - (unsigned)(v & 0xFFFFFFFFull);
            if (idx < (unsigned)n)
                atomicMax((int*)assign + idx, __float_as_int((float)tid));
        }
        if (tid < NTILES) g_count[tid] = 0;    // ready for next graph replay
    }
}

extern "C" void kernel_launch(void* const* d_in, const int* in_sizes, int n_in,
                              void* d_out, int out_size) {
    int ia = (n_in >= 2 && in_sizes[1] > in_sizes[0]) ? 1 : 0;
    const float4* anchor = (const float4*)d_in[ia];       // [N,4] f32
    const float4* gt     = (const float4*)d_in[1 - ia];   // [128,4] f32
    float* assign = (float*)d_out;                        // float32 output
    int n = in_sizes[ia] / 4;                             // 262144

    fused<<<GRID, MT>>>(anchor, gt, assign, n);
    (void)out_size;
}

// round 8
// speedup vs baseline: 1.2859x; 1.2556x over previous
#include <cuda_runtime.h>
#include <cstdint>

#define N_GT   128
#define NTX    16
#define NTILES 256
#define EXPAND 129.0f      // tile size 64 + max anchor extent 65
#define MT     256         // threads per block
#define APT    4           // anchors per thread
#define GRIDN  256         // 256*256*4 = 262144 anchors
#define PAD    32          // 256B stride: spreads g_best across LTS slices

__device__ unsigned long long g_best[N_GT * PAD];  // zero-init; reset each run
__device__ unsigned           g_done = 0;          // zero-init; reset each run

__global__ __launch_bounds__(MT) void fused(
    const float4* __restrict__ anchor,
    const float4* __restrict__ gt,
    float* __restrict__ assign, int n)
{
    __shared__ float4 s_g[N_GT];
    __shared__ float  s_ga[N_GT];
    __shared__ uint4  s_mask[NTILES];            // 128-bit GT mask per tile
    __shared__ unsigned long long s_best[N_GT];
    __shared__ int s_last;

    const int tid = threadIdx.x;
    const int b   = blockIdx.x;

    if (tid < N_GT) {
        float4 g = gt[tid];
        s_g[tid]  = g;
        s_ga[tid] = __fmul_rn(__fsub_rn(g.z, g.x), __fsub_rn(g.w, g.y));
        s_best[tid] = 0ull;
    }
    __syncthreads();

    // Build per-tile GT candidate masks (tile = tid). Conservative: covers every
    // anchor whose top-left corner lies in this tile (box within +129px window).
    {
        float tx0 = (float)((tid & (NTX - 1)) << 6);
        float ty0 = (float)((tid >> 4) << 6);
        unsigned m0 = 0, m1 = 0, m2 = 0, m3 = 0;
        #pragma unroll 4
        for (int g = 0; g < N_GT; ++g) {
            float4 G = s_g[g];                                   // LDS broadcast
            bool hit = (G.z > tx0) & (G.x < tx0 + EXPAND) &
                       (G.w > ty0) & (G.y < ty0 + EXPAND);
            unsigned bit = (unsigned)hit << (g & 31);
            if (g < 32)       m0 |= bit;
            else if (g < 64)  m1 |= bit;
            else if (g < 96)  m2 |= bit;
            else              m3 |= bit;
        }
        s_mask[tid] = make_uint4(m0, m1, m2, m3);
    }
    __syncthreads();

    // Process 4 MT-strided anchors per thread (coalesced loads/stores).
    const int base = b * (MT * APT);
    #pragma unroll
    for (int k = 0; k < APT; ++k) {
        int i = base + k * MT + tid;
        float4 a = anchor[i];
        float aarea = __fmul_rn(__fsub_rn(a.z, a.x), __fsub_rn(a.w, a.y));
        int tx = min((int)a.x >> 6, NTX - 1);
        int ty = min((int)a.y >> 6, NTX - 1);
        uint4 mm = s_mask[ty * NTX + tx];
        bool hit = false;

        #pragma unroll
        for (int w = 0; w < 4; ++w) {
            unsigned m = (w == 0) ? mm.x : (w == 1) ? mm.y : (w == 2) ? mm.z : mm.w;
            #pragma unroll 1
            while (m) {
                int g = (w << 5) + __ffs(m) - 1;
                m &= m - 1;
                float4 G = s_g[g];
                float iw = __fsub_rn(fminf(a.z, G.z), fmaxf(a.x, G.x));
                float ih = __fsub_rn(fminf(a.w, G.w), fmaxf(a.y, G.y));
                if ((iw > 0.0f) & (ih > 0.0f)) {
                    // bit-exact reference arithmetic:
                    float inter = __fmul_rn(iw, ih);
                    float u = __fsub_rn(__fadd_rn(aarea, s_ga[g]), inter);
                    float q = __fdiv_rn(inter, u);     // == jax fp32 inter/union
                    hit |= (q >= 0.3f);
                    unsigned long long key =
                        ((unsigned long long)__float_as_uint(q) << 32) |
                        (unsigned)(0xFFFFFFFFu - (unsigned)i);
                    if (key > s_best[g]) atomicMax(&s_best[g], key);
                }
            }
        }
        assign[i] = hit ? -2.0f : -1.0f;   // row result: any exact iou >= 0.3
    }
    __syncthreads();

    // Block -> global column reduction (padded table; read-check cuts atomics).
    if (tid < N_GT) {
        unsigned long long v = s_best[tid];
        if (v) {
            unsigned long long cur = g_best[tid * PAD];
            if (v > cur) atomicMax(&g_best[tid * PAD], v);
        }
    }

    // Last-finishing block claims argmax anchors and resets state for replay.
    __threadfence();
    __syncthreads();
    if (tid == 0) {
        unsigned t = atomicAdd(&g_done, 1u);
        s_last = (t == GRIDN - 1);
    }
    __syncthreads();
    if (s_last) {
        if (tid < N_GT) {
            unsigned long long v = atomicMax(&g_best[tid * PAD], 0ull); // read
            // v==0: no positive-iou pair for this gt -> reference argmax = 0
            unsigned idx = (v == 0ull) ? 0u
                         : (0xFFFFFFFFu - (unsigned)(v & 0xFFFFFFFFull));
            if (idx < (unsigned)n)
                atomicMax((int*)assign + idx, __float_as_int((float)tid));
            g_best[tid * PAD] = 0ull;      // restore zero-state invariant
        }
        __syncthreads();
        if (tid == 0) { __threadfence(); g_done = 0u; }
    }
}

extern "C" void kernel_launch(void* const* d_in, const int* in_sizes, int n_in,
                              void* d_out, int out_size) {
    int ia = (n_in >= 2 && in_sizes[1] > in_sizes[0]) ? 1 : 0;
    const float4* anchor = (const float4*)d_in[ia];       // [N,4] f32
    const float4* gt     = (const float4*)d_in[1 - ia];   // [128,4] f32
    float* assign = (float*)d_out;                        // float32 output
    int n = in_sizes[ia] / 4;                             // 262144

    fused<<<GRIDN, MT>>>(anchor, gt, assign, n);
    (void)out_size;
}

// round 10
// speedup vs baseline: 2.8809x; 2.2404x over previous
#include <cuda_runtime.h>
#include <cstdint>

#define N_GT   128
#define NTX    16
#define NTILES 256
#define MT     256         // threads per block, 1 anchor per thread
#define GRIDN  1024        // 1024*256 = 262144 anchors
#define CMAX   64          // per-tile candidate list capacity (avg ~4.6)
#define PAD    32          // 256B stride: spreads g_best across LTS slices

__device__ unsigned long long g_best[N_GT * PAD];  // zero-init; reset each run
__device__ unsigned           g_done = 0;          // zero-init; reset each run

__global__ __launch_bounds__(MT, 7) void fused(
    const float4* __restrict__ anchor,
    const float4* __restrict__ gt,
    float* __restrict__ assign, int n)
{
    __shared__ float4 s_g[N_GT];
    __shared__ float  s_ga[N_GT];
    __shared__ int    s_cnt[NTILES];
    __shared__ unsigned char s_list[NTILES * CMAX];
    __shared__ unsigned long long s_best[N_GT];
    __shared__ int s_last;

    const int tid = threadIdx.x;
    const int b   = blockIdx.x;

    s_cnt[tid] = 0;
    if (tid < N_GT) {
        float4 g = gt[tid];
        s_g[tid]  = g;
        s_ga[tid] = __fmul_rn(__fsub_rn(g.z, g.x), __fsub_rn(g.w, g.y));
        s_best[tid] = 0ull;
    }
    __syncthreads();

    // GT-range scatter: thread per GT marks every tile whose 193px window it
    // intersects (covers all anchors with top-left corner in that tile; anchor
    // extent <= 65, tile 64 -> window 129; bounds conservatively rounded).
    if (tid < N_GT) {
        float4 G = s_g[tid];
        int txlo = max(0, (int)floorf((G.x - 129.0f) * 0.015625f));
        int txhi = min(NTX - 1, (int)floorf(G.z * 0.015625f));
        int tylo = max(0, (int)floorf((G.y - 129.0f) * 0.015625f));
        int tyhi = min(NTX - 1, (int)floorf(G.w * 0.015625f));
        for (int ty = tylo; ty <= tyhi; ++ty)
            for (int tx = txlo; tx <= txhi; ++tx) {
                int t = ty * NTX + tx;
                int slot = atomicAdd(&s_cnt[t], 1);
                if (slot < CMAX) s_list[t * CMAX + slot] = (unsigned char)tid;
            }
    }
    __syncthreads();

    // One anchor per thread; branch-free candidate body (q computed always;
    // q==0 exactly matches the reference for non-overlapping pairs).
    const int i = b * MT + tid;
    if (i < n) {
        float4 a = anchor[i];
        float aarea = __fmul_rn(__fsub_rn(a.z, a.x), __fsub_rn(a.w, a.y));
        int tx = min((int)a.x >> 6, NTX - 1);
        int ty = min((int)a.y >> 6, NTX - 1);
        int t  = ty * NTX + tx;
        int cnt = s_cnt[t];
        bool hit = false;
        unsigned lowkey = ~(unsigned)i;

        if (cnt <= CMAX) {
            for (int c = 0; c < cnt; ++c) {
                int g = s_list[t * CMAX + c];
                float4 G = s_g[g];
                float iw = fmaxf(__fsub_rn(fminf(a.z, G.z), fmaxf(a.x, G.x)), 0.0f);
                float ih = fmaxf(__fsub_rn(fminf(a.w, G.w), fmaxf(a.y, G.y)), 0.0f);
                float inter = __fmul_rn(iw, ih);
                float u = __fsub_rn(__fadd_rn(aarea, s_ga[g]), inter);
                float q = __fdiv_rn(inter, u);          // == jax fp32 inter/union
                hit |= (q >= 0.3f);
                unsigned long long key =
                    ((unsigned long long)__float_as_uint(q) << 32) | lowkey;
                if (key > s_best[g]) atomicMax(&s_best[g], key);
            }
        } else {                                        // overflow fallback (cold)
            for (int g = 0; g < N_GT; ++g) {
                float4 G = s_g[g];
                float iw = fmaxf(__fsub_rn(fminf(a.z, G.z), fmaxf(a.x, G.x)), 0.0f);
                float ih = fmaxf(__fsub_rn(fminf(a.w, G.w), fmaxf(a.y, G.y)), 0.0f);
                float inter = __fmul_rn(iw, ih);
                float u = __fsub_rn(__fadd_rn(aarea, s_ga[g]), inter);
                float q = __fdiv_rn(inter, u);
                hit |= (q >= 0.3f);
                unsigned long long key =
                    ((unsigned long long)__float_as_uint(q) << 32) | lowkey;
                if (key > s_best[g]) atomicMax(&s_best[g], key);
            }
        }
        assign[i] = hit ? -2.0f : -1.0f;    // row result: any exact iou >= 0.3
    }
    __syncthreads();

    // Block -> global column reduction (padded table; read-check cuts atomics).
    if (tid < N_GT) {
        unsigned long long v = s_best[tid];
        if (v) {
            unsigned long long cur = g_best[tid * PAD];
            if (v > cur) atomicMax(&g_best[tid * PAD], v);
        }
    }

    // Last-finishing block claims argmax anchors and resets state for replay.
    __threadfence();
    __syncthreads();
    if (tid == 0) {
        unsigned tkt = atomicAdd(&g_done, 1u);
        s_last = (tkt == GRIDN - 1);
    }
    __syncthreads();
    if (s_last) {
        if (tid < N_GT) {
            unsigned long long v = atomicMax(&g_best[tid * PAD], 0ull); // read
            // v==0: no positive-iou pair -> reference argmax = index 0
            unsigned idx = (v == 0ull) ? 0u
                         : (0xFFFFFFFFu - (unsigned)(v & 0xFFFFFFFFull));
            if (idx < (unsigned)n)
                atomicMax((int*)assign + idx, __float_as_int((float)tid));
            g_best[tid * PAD] = 0ull;       // restore zero-state invariant
        }
        __syncthreads();
        if (tid == 0) { __threadfence(); g_done = 0u; }
    }
}

extern "C" void kernel_launch(void* const* d_in, const int* in_sizes, int n_in,
                              void* d_out, int out_size) {
    int ia = (n_in >= 2 && in_sizes[1] > in_sizes[0]) ? 1 : 0;
    const float4* anchor = (const float4*)d_in[ia];       // [N,4] f32
    const float4* gt     = (const float4*)d_in[1 - ia];   // [128,4] f32
    float* assign = (float*)d_out;                        // float32 output
    int n = in_sizes[ia] / 4;                             // 262144

    fused<<<GRIDN, MT>>>(anchor, gt, assign, n);
    (void)out_size;
}

// round 11
// speedup vs baseline: 3.3665x; 1.1686x over previous
#include <cuda_runtime.h>
#include <cstdint>

#define N_GT    128
#define NTX2    32          // 32x32 tiles of 32px
#define NTILES2 1024
#define MT      256
#define APT     2
#define GRIDN   512         // 512*256*2 = 262144 anchors
#define CMAX    24          // per-tile candidate cap (mean 4.65, tail ~20)
#define PAD     32          // 256B stride: spreads g_best across LTS slices

__device__ unsigned long long g_best[N_GT * PAD];  // zero-init; reset each run
__device__ unsigned           g_done = 0;          // zero-init; reset each run

__global__ __launch_bounds__(MT, 4) void fused(
    const float4* __restrict__ anchor,
    const float4* __restrict__ gt,
    float* __restrict__ assign, int n)
{
    __shared__ float4 s_g[N_GT];
    __shared__ float  s_ga[N_GT];
    __shared__ int    s_cnt[NTILES2];
    __shared__ unsigned char s_list[NTILES2 * CMAX];
    __shared__ unsigned long long s_best[N_GT];
    __shared__ int s_last;

    const int tid = threadIdx.x;
    const int b   = blockIdx.x;

    #pragma unroll
    for (int r = 0; r < NTILES2 / MT; ++r) s_cnt[r * MT + tid] = 0;
    if (tid < N_GT) {
        float4 g = gt[tid];
        s_g[tid]  = g;
        s_ga[tid] = __fmul_rn(__fsub_rn(g.z, g.x), __fsub_rn(g.w, g.y));
        s_best[tid] = 0ull;
    }
    __syncthreads();

    // GT-range scatter, 2 threads per GT (split ty range). Tile (tx,ty) gets gt
    // iff some anchor with top-left corner in the tile could overlap it:
    // anchor box subset of [tx0, tx0+32+65) -> window G.x-97 < tx0 < G.z.
    {
        int g = tid >> 1;
        float4 G = s_g[g];
        int txlo = max(0, ((int)G.x - 97) >> 5);          // conservative floors
        int txhi = min(NTX2 - 1, (int)G.z >> 5);
        int tylo = max(0, ((int)G.y - 97) >> 5);
        int tyhi = min(NTX2 - 1, (int)G.w >> 5);
        int nty  = tyhi - tylo + 1;
        int h    = tid & 1;
        int y0   = tylo + (h ? (nty + 1) >> 1 : 0);
        int y1   = h ? tyhi : (tylo + ((nty + 1) >> 1) - 1);
        for (int ty = y0; ty <= y1; ++ty)
            for (int tx = txlo; tx <= txhi; ++tx) {
                int t = (ty << 5) + tx;
                int slot = atomicAdd(&s_cnt[t], 1);
                if (slot < CMAX) s_list[t * CMAX + slot] = (unsigned char)g;
            }
    }
    __syncthreads();

    // APT anchors per thread; candidate loop per anchor (branch-free body).
    const int i0 = b * (MT * APT) + tid;
    #pragma unroll
    for (int k = 0; k < APT; ++k) {
        int i = i0 + k * MT;
        float4 a = anchor[i];
        float aarea = __fmul_rn(__fsub_rn(a.z, a.x), __fsub_rn(a.w, a.y));
        int t = (((int)a.y >> 5) << 5) + ((int)a.x >> 5);
        int cnt = s_cnt[t];
        bool hit = false;
        unsigned lowkey = ~(unsigned)i;

        if (cnt <= CMAX) {
            for (int c = 0; c < cnt; ++c) {
                int g = s_list[t * CMAX + c];
                float4 G = s_g[g];
                float iw = fmaxf(__fsub_rn(fminf(a.z, G.z), fmaxf(a.x, G.x)), 0.0f);
                float ih = fmaxf(__fsub_rn(fminf(a.w, G.w), fmaxf(a.y, G.y)), 0.0f);
                float inter = __fmul_rn(iw, ih);
                float u = __fsub_rn(__fadd_rn(aarea, s_ga[g]), inter);
                float q = __fdiv_rn(inter, u);          // == jax fp32 inter/union
                hit |= (q >= 0.3f);
                unsigned long long key =
                    ((unsigned long long)__float_as_uint(q) << 32) | lowkey;
                if (key > s_best[g]) atomicMax(&s_best[g], key);
            }
        } else {                                        // overflow fallback (cold)
            for (int g = 0; g < N_GT; ++g) {
                float4 G = s_g[g];
                float iw = fmaxf(__fsub_rn(fminf(a.z, G.z), fmaxf(a.x, G.x)), 0.0f);
                float ih = fmaxf(__fsub_rn(fminf(a.w, G.w), fmaxf(a.y, G.y)), 0.0f);
                float inter = __fmul_rn(iw, ih);
                float u = __fsub_rn(__fadd_rn(aarea, s_ga[g]), inter);
                float q = __fdiv_rn(inter, u);
                hit |= (q >= 0.3f);
                unsigned long long key =
                    ((unsigned long long)__float_as_uint(q) << 32) | lowkey;
                if (key > s_best[g]) atomicMax(&s_best[g], key);
            }
        }
        assign[i] = hit ? -2.0f : -1.0f;    // row result: any exact iou >= 0.3
    }
    __syncthreads();

    // Block -> global column reduction (padded table; read-check cuts atomics).
    if (tid < N_GT) {
        unsigned long long v = s_best[tid];
        if (v) {
            unsigned long long cur = g_best[tid * PAD];
            if (v > cur) atomicMax(&g_best[tid * PAD], v);
        }
    }

    // Last-finishing block claims argmax anchors and resets state for replay.
    __threadfence();
    __syncthreads();
    if (tid == 0) {
        unsigned tkt = atomicAdd(&g_done, 1u);
        s_last = (tkt == GRIDN - 1);
    }
    __syncthreads();
    if (s_last) {
        if (tid < N_GT) {
            unsigned long long v = atomicMax(&g_best[tid * PAD], 0ull); // read
            // v==0: no positive-iou pair -> reference argmax = index 0
            unsigned idx = (v == 0ull) ? 0u
                         : (0xFFFFFFFFu - (unsigned)(v & 0xFFFFFFFFull));
            if (idx < (unsigned)n)
                atomicMax((int*)assign + idx, __float_as_int((float)tid));
            g_best[tid * PAD] = 0ull;       // restore zero-state invariant
        }
        __syncthreads();
        if (tid == 0) { __threadfence(); g_done = 0u; }
    }
}

extern "C" void kernel_launch(void* const* d_in, const int* in_sizes, int n_in,
                              void* d_out, int out_size) {
    int ia = (n_in >= 2 && in_sizes[1] > in_sizes[0]) ? 1 : 0;
    const float4* anchor = (const float4*)d_in[ia];       // [N,4] f32
    const float4* gt     = (const float4*)d_in[1 - ia];   // [128,4] f32
    float* assign = (float*)d_out;                        // float32 output
    int n = in_sizes[ia] / 4;                             // 262144

    fused<<<GRIDN, MT>>>(anchor, gt, assign, n);
    (void)out_size;
}